// round 10
// baseline (speedup 1.0000x reference)
#include <cuda_runtime.h>
#include <cuda_fp16.h>
#include <math_constants.h>
#include <mma.h>

using namespace nvcuda;

#define N_NODES   262144
#define D_IN      512
#define B_GRAPHS  256
#define GATES     2048      // 4*D_IN
#define K_COMB    1024      // combined K (h:512 | r:512)
#define STEPS     6
#define CHUNK     896       // nodes per attention block (293 blocks = 1 wave @ 2 CTA/SM)
#define N_CHUNKS  ((N_NODES + CHUNK - 1) / CHUNK)   // 293
#define MAX_SLOTS 8

// ----------------- device scratch (no runtime allocation allowed) -----------
__device__ __align__(16) float  g_W[GATES * K_COMB];
__device__ __align__(16) float  g_bias[GATES];
__device__ __align__(16) float  g_hr[B_GRAPHS * 1024];    // [h | r] = q_star
__device__ __align__(16) float  g_c[B_GRAPHS * D_IN];
__device__ __align__(16) float  g_gates[B_GRAPHS * GATES];
__device__ __align__(16) __half g_x16[(size_t)N_NODES * D_IN];  // 256 MB fp16 copy
__device__ int g_off[B_GRAPHS + 1];
__device__ __align__(16) float g_part_r[B_GRAPHS * MAX_SLOTS * D_IN];
__device__ float g_part_m[B_GRAPHS * MAX_SLOTS];
__device__ float g_part_d[B_GRAPHS * MAX_SLOTS];

// ----------------------------- helpers --------------------------------------
__device__ __forceinline__ float sigm(float v) {
    return 1.0f / (1.0f + __expf(-v));
}
__device__ __forceinline__ float tf32r(float v) {
    unsigned u;
    asm("cvt.rna.tf32.f32 %0, %1;" : "=r"(u) : "f"(v));
    return __uint_as_float(u);
}
__device__ __forceinline__ void cp_async16(void* smem_dst, const void* gmem_src) {
    unsigned s = (unsigned)__cvta_generic_to_shared(smem_dst);
    asm volatile("cp.async.cg.shared.global [%0], [%1], 16;" :: "r"(s), "l"(gmem_src) : "memory");
}
#define CP_COMMIT() asm volatile("cp.async.commit_group;" ::: "memory")
#define CP_WAIT3()  asm volatile("cp.async.wait_group 3;" ::: "memory")

// --------------------------- prep kernels -----------------------------------
__global__ void prep_w_kernel(const float* __restrict__ w_ih,
                              const float* __restrict__ w_hh,
                              const float* __restrict__ b_ih,
                              const float* __restrict__ b_hh) {
    int idx = blockIdx.x * blockDim.x + threadIdx.x;
    int n = idx >> 10;
    int k = idx & 1023;
    float v = w_ih[n * 1024 + k];
    if (k < 512) v += w_hh[n * 512 + k];
    g_W[idx] = tf32r(v);
    if (idx < GATES) g_bias[idx] = b_ih[idx] + b_hh[idx];
}

__global__ void offsets_kernel(const int* __restrict__ batch) {
    int t = blockIdx.x * blockDim.x + threadIdx.x;
    if (t > B_GRAPHS) return;
    int lo = 0, hi = N_NODES;
    while (lo < hi) {
        int mid = (lo + hi) >> 1;
        if (batch[mid] < t) lo = mid + 1; else hi = mid;
    }
    g_off[t] = lo;
}

// Step 0: q_star = 0, h = 0 -> gates = bias (identical for every graph)
__global__ void lstm_init_kernel() {
    int b = blockIdx.x;
    int d = threadIdx.x;
    float i = sigm(g_bias[d]);
    float g = tanhf(g_bias[1024 + d]);
    float o = sigm(g_bias[1536 + d]);
    float c = i * g;
    g_c[b * D_IN + d]  = c;
    g_hr[b * 1024 + d] = o * tanhf(c);
}

// ----------------- GEMM (tf32 tensor cores): gates = hr @ W^T ----------------
__global__ void __launch_bounds__(256) gemm_tc_kernel() {
    __shared__ __align__(16) float sA[64][40];
    __shared__ __align__(16) float sB[64][40];

    const int bm = blockIdx.y * 64;
    const int bn = blockIdx.x * 64;
    const int tid = threadIdx.x;
    const int w   = tid >> 5;
    const int mt  = w & 3;
    const int ng  = w >> 2;

    wmma::fragment<wmma::accumulator, 16, 16, 8, float> cf[2];
    wmma::fill_fragment(cf[0], 0.0f);
    wmma::fill_fragment(cf[1], 0.0f);

    const int row = tid >> 2;
    const int col = (tid & 3) * 8;

    const float* Ag = g_hr + (bm + row) * K_COMB + col;
    const float* Bg = g_W  + (bn + row) * K_COMB + col;

    float4 a0 = *(const float4*)(Ag);
    float4 a1 = *(const float4*)(Ag + 4);
    float4 b0 = *(const float4*)(Bg);
    float4 b1 = *(const float4*)(Bg + 4);

    for (int k0 = 0; k0 < K_COMB; k0 += 32) {
        sA[row][col + 0] = tf32r(a0.x); sA[row][col + 1] = tf32r(a0.y);
        sA[row][col + 2] = tf32r(a0.z); sA[row][col + 3] = tf32r(a0.w);
        sA[row][col + 4] = tf32r(a1.x); sA[row][col + 5] = tf32r(a1.y);
        sA[row][col + 6] = tf32r(a1.z); sA[row][col + 7] = tf32r(a1.w);
        sB[row][col + 0] = b0.x; sB[row][col + 1] = b0.y;
        sB[row][col + 2] = b0.z; sB[row][col + 3] = b0.w;
        sB[row][col + 4] = b1.x; sB[row][col + 5] = b1.y;
        sB[row][col + 6] = b1.z; sB[row][col + 7] = b1.w;
        __syncthreads();

        if (k0 + 32 < K_COMB) {
            a0 = *(const float4*)(Ag + k0 + 32);
            a1 = *(const float4*)(Ag + k0 + 36);
            b0 = *(const float4*)(Bg + k0 + 32);
            b1 = *(const float4*)(Bg + k0 + 36);
        }

        #pragma unroll
        for (int kk = 0; kk < 32; kk += 8) {
            wmma::fragment<wmma::matrix_a, 16, 16, 8, wmma::precision::tf32, wmma::row_major> af;
            wmma::load_matrix_sync(af, &sA[mt * 16][kk], 40);
            #pragma unroll
            for (int t = 0; t < 2; t++) {
                wmma::fragment<wmma::matrix_b, 16, 16, 8, wmma::precision::tf32, wmma::col_major> bf;
                wmma::load_matrix_sync(bf, &sB[(ng * 2 + t) * 16][kk], 40);
                wmma::mma_sync(cf[t], af, bf, cf[t]);
            }
        }
        __syncthreads();
    }

    #pragma unroll
    for (int t = 0; t < 2; t++)
        wmma::store_matrix_sync(&g_gates[(bm + mt * 16) * GATES + bn + (ng * 2 + t) * 16],
                                cf[t], GATES, wmma::mem_row_major);
}

// --------------------------- LSTM pointwise (adds bias) ----------------------
__global__ void lstm_pw_kernel() {
    int idx = blockIdx.x * blockDim.x + threadIdx.x;
    int b = idx >> 9;
    int d = idx & 511;
    const float* gr = g_gates + b * GATES + d;
    float i = sigm(gr[0]    + g_bias[d]);
    float f = sigm(gr[512]  + g_bias[512 + d]);
    float g = tanhf(gr[1024] + g_bias[1024 + d]);
    float o = sigm(gr[1536] + g_bias[1536 + d]);
    float c = f * g_c[idx] + i * g;
    g_c[idx] = c;
    g_hr[b * 1024 + d] = o * tanhf(c);
}

// ---------- attention step 0: fp32 sweep + write fp16 copy of x --------------
// Warp-per-node online softmax; col layout slot j*4+c <-> column 128*j+4*lane+c.
__global__ void __launch_bounds__(512, 2) attn0_kernel(const float* __restrict__ x) {
    const int chunk = blockIdx.x;
    const int i0 = chunk * CHUNK;
    const int i1 = min(i0 + CHUNK, N_NODES);
    const int tid  = threadIdx.x;
    const int wid  = tid >> 5;
    const int lane = tid & 31;

    __shared__ __align__(16) float sm_q[D_IN];
    __shared__ float  sm_m[16], sm_d[16], sm_scale[16];
    __shared__ __align__(16) float4 sm_r[16][128];

    int lo = 0, hi = B_GRAPHS;
    while (lo < hi) {
        int mid = (lo + hi) >> 1;
        if (g_off[mid + 1] <= i0) lo = mid + 1; else hi = mid;
    }
    int b = lo;

    while (b < B_GRAPHS && g_off[b] < i1) {
        const int s0 = max(g_off[b], i0);
        const int s1 = min(g_off[b + 1], i1);
        if (s1 > s0) {
            sm_q[tid] = g_hr[b * 1024 + tid];
            __syncthreads();
            const float4* q4 = (const float4*)sm_q;

            float m = -CUDART_INF_F, denom = 0.0f;
            float r[16];
            #pragma unroll
            for (int k = 0; k < 16; k++) r[k] = 0.0f;

            for (int n = s0 + wid; n < s1; n += 16) {
                const float4* xr = (const float4*)(x + (size_t)n * D_IN);
                float xv[16];
                #pragma unroll
                for (int j = 0; j < 4; j++) {
                    float4 v = __ldcs(xr + j * 32 + lane);
                    xv[j*4+0] = v.x; xv[j*4+1] = v.y;
                    xv[j*4+2] = v.z; xv[j*4+3] = v.w;
                }
                {
                    uint2* row16 = (uint2*)(g_x16 + (size_t)n * D_IN);
                    #pragma unroll
                    for (int j = 0; j < 4; j++) {
                        __half2 h0 = __floats2half2_rn(xv[j*4+0], xv[j*4+1]);
                        __half2 h1 = __floats2half2_rn(xv[j*4+2], xv[j*4+3]);
                        uint2 px;
                        px.x = *(unsigned*)&h0;
                        px.y = *(unsigned*)&h1;
                        row16[j * 32 + lane] = px;
                    }
                }

                float p = 0.0f;
                #pragma unroll
                for (int j = 0; j < 4; j++) {
                    float4 qv = q4[j * 32 + lane];
                    p = fmaf(xv[j*4+0], qv.x, p);
                    p = fmaf(xv[j*4+1], qv.y, p);
                    p = fmaf(xv[j*4+2], qv.z, p);
                    p = fmaf(xv[j*4+3], qv.w, p);
                }
                #pragma unroll
                for (int o = 16; o; o >>= 1) p += __shfl_xor_sync(0xffffffffu, p, o);

                const float mn = fmaxf(m, p);
                const float sc = __expf(m - mn);
                const float wg = __expf(p - mn);
                denom = fmaf(denom, sc, wg);
                #pragma unroll
                for (int k = 0; k < 16; k++) r[k] = fmaf(r[k], sc, wg * xv[k]);
                m = mn;
            }

            if (lane == 0) { sm_m[wid] = m; sm_d[wid] = denom; }
            #pragma unroll
            for (int j = 0; j < 4; j++)
                sm_r[wid][j * 32 + lane] =
                    make_float4(r[j*4+0], r[j*4+1], r[j*4+2], r[j*4+3]);
            __syncthreads();

            float M = -CUDART_INF_F;
            #pragma unroll
            for (int w = 0; w < 16; w++) M = fmaxf(M, sm_m[w]);
            if (tid < 16)
                sm_scale[tid] = (sm_m[tid] == -CUDART_INF_F) ? 0.0f : __expf(sm_m[tid] - M);
            __syncthreads();

            float Dn = 0.0f, num = 0.0f;
            #pragma unroll
            for (int w = 0; w < 16; w++) {
                Dn  += sm_d[w] * sm_scale[w];
                num  = fmaf(((const float*)sm_r[w])[tid], sm_scale[w], num);
            }

            const int slot = chunk - g_off[b] / CHUNK;
            g_part_r[(b * MAX_SLOTS + slot) * D_IN + tid] = num;
            if (tid == 0) {
                g_part_m[b * MAX_SLOTS + slot] = M;
                g_part_d[b * MAX_SLOTS + slot] = Dn;
            }
            __syncthreads();
        }
        b++;
    }
}

// ---- attention steps 1..5: fp16, per-warp cp.async ring (depth 4, no bars) --
// Warp owns nodes n0, n0+16, ... Each lane async-copies exactly the two 16B
// segments it later reads (halves [8L,8L+8) and [256+8L,+8)): thread-local
// dataflow, wait_group only. Ring: 16 warps x 4 stages x 1KB = 64KB dyn smem.
__global__ void __launch_bounds__(512, 2) attn16_kernel() {
    extern __shared__ __align__(16) __half ring[];   // [16][4][512]
    __shared__ __align__(16) float sm_q[D_IN];
    __shared__ float  sm_m[16], sm_d[16], sm_scale[16];
    __shared__ __align__(16) float4 sm_r[16][128];

    const int chunk = blockIdx.x;
    const int i0 = chunk * CHUNK;
    const int i1 = min(i0 + CHUNK, N_NODES);
    const int tid  = threadIdx.x;
    const int wid  = tid >> 5;
    const int lane = tid & 31;

    __half* wring = ring + wid * 4 * 512;

    int lo = 0, hi = B_GRAPHS;
    while (lo < hi) {
        int mid = (lo + hi) >> 1;
        if (g_off[mid + 1] <= i0) lo = mid + 1; else hi = mid;
    }
    int b = lo;

    while (b < B_GRAPHS && g_off[b] < i1) {
        const int s0 = max(g_off[b], i0);
        const int s1 = min(g_off[b + 1], i1);
        if (s1 > s0) {
            sm_q[tid] = g_hr[b * 1024 + tid];
            __syncthreads();
            float qf[16];
            #pragma unroll
            for (int k = 0; k < 8; k++) qf[k]     = sm_q[8 * lane + k];
            #pragma unroll
            for (int k = 0; k < 8; k++) qf[8 + k] = sm_q[256 + 8 * lane + k];

            float m = -CUDART_INF_F, denom = 0.0f;
            float r[16];
            #pragma unroll
            for (int k = 0; k < 16; k++) r[k] = 0.0f;

            const int n0 = s0 + wid;
            const int total = (n0 < s1) ? ((s1 - n0 + 15) >> 4) : 0;

            // prologue: stages 0..3 (always 4 commits to keep group count fixed)
            #pragma unroll
            for (int k = 0; k < 4; k++) {
                if (k < total) {
                    const __half* src = g_x16 + (size_t)(n0 + (k << 4)) * D_IN;
                    __half* dst = wring + k * 512;
                    cp_async16(dst + 8 * lane,       src + 8 * lane);
                    cp_async16(dst + 256 + 8 * lane, src + 256 + 8 * lane);
                }
                CP_COMMIT();
            }

            for (int i = 0; i < total; i++) {
                CP_WAIT3();                        // row i complete
                const __half* row = wring + (i & 3) * 512;
                uint4 u0 = *(const uint4*)(row + 8 * lane);
                uint4 u1 = *(const uint4*)(row + 256 + 8 * lane);

                float xf[16];
                {
                    const unsigned* u = (const unsigned*)&u0;
                    #pragma unroll
                    for (int t = 0; t < 4; t++) {
                        float2 f = __half22float2(*(const __half2*)&u[t]);
                        xf[t*2+0] = f.x; xf[t*2+1] = f.y;
                    }
                    const unsigned* v = (const unsigned*)&u1;
                    #pragma unroll
                    for (int t = 0; t < 4; t++) {
                        float2 f = __half22float2(*(const __half2*)&v[t]);
                        xf[8+t*2+0] = f.x; xf[8+t*2+1] = f.y;
                    }
                }

                float p = 0.0f;
                #pragma unroll
                for (int k = 0; k < 16; k++) p = fmaf(xf[k], qf[k], p);
                #pragma unroll
                for (int o = 16; o; o >>= 1) p += __shfl_xor_sync(0xffffffffu, p, o);

                const float mn = fmaxf(m, p);
                const float sc = __expf(m - mn);
                const float wg = __expf(p - mn);
                denom = fmaf(denom, sc, wg);
                #pragma unroll
                for (int k = 0; k < 16; k++) r[k] = fmaf(r[k], sc, wg * xf[k]);
                m = mn;

                // issue row i+4, always commit (possibly empty group)
                const int k4 = i + 4;
                if (k4 < total) {
                    const __half* src = g_x16 + (size_t)(n0 + (k4 << 4)) * D_IN;
                    __half* dst = wring + (k4 & 3) * 512;
                    cp_async16(dst + 8 * lane,       src + 8 * lane);
                    cp_async16(dst + 256 + 8 * lane, src + 256 + 8 * lane);
                }
                CP_COMMIT();
            }

            if (lane == 0) { sm_m[wid] = m; sm_d[wid] = denom; }
            {
                float* dst = (float*)sm_r[wid];
                #pragma unroll
                for (int k = 0; k < 8; k++) dst[8 * lane + k]       = r[k];
                #pragma unroll
                for (int k = 0; k < 8; k++) dst[256 + 8 * lane + k] = r[8 + k];
            }
            __syncthreads();

            float M = -CUDART_INF_F;
            #pragma unroll
            for (int w = 0; w < 16; w++) M = fmaxf(M, sm_m[w]);
            if (tid < 16)
                sm_scale[tid] = (sm_m[tid] == -CUDART_INF_F) ? 0.0f : __expf(sm_m[tid] - M);
            __syncthreads();

            float Dn = 0.0f, num = 0.0f;
            #pragma unroll
            for (int w = 0; w < 16; w++) {
                Dn  += sm_d[w] * sm_scale[w];
                num  = fmaf(((const float*)sm_r[w])[tid], sm_scale[w], num);
            }

            const int slot = chunk - g_off[b] / CHUNK;
            g_part_r[(b * MAX_SLOTS + slot) * D_IN + tid] = num;
            if (tid == 0) {
                g_part_m[b * MAX_SLOTS + slot] = M;
                g_part_d[b * MAX_SLOTS + slot] = Dn;
            }
            __syncthreads();
        }
        b++;
    }
}

// ------------------ attention pass 2: per-graph merge ------------------------
// On the final step also writes q_star = [h | r] straight to out.
__global__ void attn_merge_kernel(float* __restrict__ out) {
    const int b   = blockIdx.x;
    const int tid = threadIdx.x;
    const int o0 = g_off[b], o1 = g_off[b + 1];
    float res = 0.0f;
    if (o1 > o0) {
        const int J = (o1 - 1) / CHUNK - o0 / CHUNK + 1;
        float M = -CUDART_INF_F;
        for (int j = 0; j < J; j++) M = fmaxf(M, g_part_m[b * MAX_SLOTS + j]);
        float D = 0.0f, acc = 0.0f;
        for (int j = 0; j < J; j++) {
            const float s = __expf(g_part_m[b * MAX_SLOTS + j] - M);
            D   = fmaf(g_part_d[b * MAX_SLOTS + j], s, D);
            acc = fmaf(g_part_r[(b * MAX_SLOTS + j) * D_IN + tid], s, acc);
        }
        res = acc / (D + 1e-16f);
    }
    g_hr[b * 1024 + 512 + tid] = res;
    if (out) {
        out[b * 1024 + tid]       = g_hr[b * 1024 + tid];   // h half
        out[b * 1024 + 512 + tid] = res;                    // r half
    }
}

// ------------------------------- launch --------------------------------------
extern "C" void kernel_launch(void* const* d_in, const int* in_sizes, int n_in,
                              void* d_out, int out_size) {
    const float* x     = (const float*)d_in[0];
    const int*   batch = (const int*)d_in[1];
    const float* w_ih  = (const float*)d_in[2];
    const float* w_hh  = (const float*)d_in[3];
    const float* b_ih  = (const float*)d_in[4];
    const float* b_hh  = (const float*)d_in[5];
    float* out = (float*)d_out;

    const int ring_smem = 16 * 4 * D_IN * sizeof(__half);   // 64 KB
    cudaFuncSetAttribute(attn16_kernel,
                         cudaFuncAttributeMaxDynamicSharedMemorySize, ring_smem);

    prep_w_kernel<<<(GATES * K_COMB) / 256, 256>>>(w_ih, w_hh, b_ih, b_hh);
    offsets_kernel<<<2, 160>>>(batch);
    lstm_init_kernel<<<B_GRAPHS, 512>>>();

    for (int s = 0; s < STEPS; s++) {
        if (s > 0) {
            gemm_tc_kernel<<<dim3(32, 4), 256>>>();
            lstm_pw_kernel<<<(B_GRAPHS * D_IN) / 512, 512>>>();
        }
        if (s == 0)
            attn0_kernel<<<N_CHUNKS, 512>>>(x);
        else
            attn16_kernel<<<N_CHUNKS, 512, ring_smem>>>();
        attn_merge_kernel<<<B_GRAPHS, 512>>>(s == STEPS - 1 ? out : nullptr);
    }
}

// round 11
// speedup vs baseline: 1.2837x; 1.2837x over previous
#include <cuda_runtime.h>
#include <cuda_fp16.h>
#include <math_constants.h>
#include <mma.h>

using namespace nvcuda;

#define N_NODES   262144
#define D_IN      512
#define B_GRAPHS  256
#define GATES     2048      // 4*D_IN
#define K_COMB    1024      // combined K (h:512 | r:512)
#define STEPS     6
#define CHUNK     896       // nodes per attention block (293 blocks = 1 wave @ 2 CTA/SM)
#define N_CHUNKS  ((N_NODES + CHUNK - 1) / CHUNK)   // 293
#define MAX_SLOTS 8

// ----------------- device scratch (no runtime allocation allowed) -----------
__device__ __align__(16) __half g_W16[GATES * K_COMB];    // fp16 combined weights (4 MB)
__device__ __align__(16) float  g_bias[GATES];
__device__ __align__(16) float  g_hr[B_GRAPHS * 1024];    // [h | r] = q_star (fp32)
__device__ __align__(16) __half g_hr16[B_GRAPHS * 1024];  // fp16 copy for GEMM
__device__ __align__(16) float  g_c[B_GRAPHS * D_IN];
__device__ __align__(16) float  g_gates[B_GRAPHS * GATES];
__device__ __align__(16) __half g_x16[(size_t)N_NODES * D_IN];  // 256 MB fp16 copy
__device__ int g_off[B_GRAPHS + 1];
__device__ __align__(16) float g_part_r[B_GRAPHS * MAX_SLOTS * D_IN];
__device__ float g_part_m[B_GRAPHS * MAX_SLOTS];
__device__ float g_part_d[B_GRAPHS * MAX_SLOTS];

// ----------------------------- helpers --------------------------------------
__device__ __forceinline__ float sigm(float v) {
    return 1.0f / (1.0f + __expf(-v));
}

// --------------------------- prep kernels -----------------------------------
__global__ void prep_w_kernel(const float* __restrict__ w_ih,
                              const float* __restrict__ w_hh,
                              const float* __restrict__ b_ih,
                              const float* __restrict__ b_hh) {
    int idx = blockIdx.x * blockDim.x + threadIdx.x;
    int n = idx >> 10;
    int k = idx & 1023;
    float v = w_ih[n * 1024 + k];
    if (k < 512) v += w_hh[n * 512 + k];
    g_W16[idx] = __float2half_rn(v);
    if (idx < GATES) g_bias[idx] = b_ih[idx] + b_hh[idx];
}

__global__ void offsets_kernel(const int* __restrict__ batch) {
    int t = blockIdx.x * blockDim.x + threadIdx.x;
    if (t > B_GRAPHS) return;
    int lo = 0, hi = N_NODES;
    while (lo < hi) {
        int mid = (lo + hi) >> 1;
        if (batch[mid] < t) lo = mid + 1; else hi = mid;
    }
    g_off[t] = lo;
}

// Step 0: q_star = 0, h = 0 -> gates = bias (identical for every graph)
__global__ void lstm_init_kernel() {
    int b = blockIdx.x;
    int d = threadIdx.x;
    float i = sigm(g_bias[d]);
    float g = tanhf(g_bias[1024 + d]);
    float o = sigm(g_bias[1536 + d]);
    float c = i * g;
    float h = o * tanhf(c);
    g_c[b * D_IN + d]  = c;
    g_hr[b * 1024 + d] = h;
    g_hr16[b * 1024 + d] = __float2half_rn(h);
}

// ------------- GEMM (fp16 HMMA, fp32 accum): gates = hr @ W^T ----------------
// M=256, N=2048, K=1024. CTA tile 64x64, 8 warps, warp = 1x2 m16n16k16 tiles.
__global__ void __launch_bounds__(256) gemm_tc_kernel() {
    __shared__ __align__(16) __half sA[64][40];
    __shared__ __align__(16) __half sB[64][40];

    const int bm = blockIdx.y * 64;        // gridDim.y = 4
    const int bn = blockIdx.x * 64;        // gridDim.x = 32
    const int tid = threadIdx.x;
    const int w   = tid >> 5;
    const int mt  = w & 3;
    const int ng  = w >> 2;

    wmma::fragment<wmma::accumulator, 16, 16, 16, float> cf[2];
    wmma::fill_fragment(cf[0], 0.0f);
    wmma::fill_fragment(cf[1], 0.0f);

    const int row = tid >> 2;              // 0..63
    const int col = (tid & 3) * 8;         // halves: 0,8,16,24

    const __half* Ag = g_hr16 + (bm + row) * K_COMB + col;
    const __half* Bg = g_W16  + (bn + row) * K_COMB + col;

    uint4 a = *(const uint4*)(Ag);
    uint4 bvec = *(const uint4*)(Bg);

    for (int k0 = 0; k0 < K_COMB; k0 += 32) {
        *(uint4*)&sA[row][col] = a;
        *(uint4*)&sB[row][col] = bvec;
        __syncthreads();

        if (k0 + 32 < K_COMB) {
            a    = *(const uint4*)(Ag + k0 + 32);
            bvec = *(const uint4*)(Bg + k0 + 32);
        }

        #pragma unroll
        for (int kk = 0; kk < 32; kk += 16) {
            wmma::fragment<wmma::matrix_a, 16, 16, 16, __half, wmma::row_major> af;
            wmma::load_matrix_sync(af, &sA[mt * 16][kk], 40);
            #pragma unroll
            for (int t = 0; t < 2; t++) {
                wmma::fragment<wmma::matrix_b, 16, 16, 16, __half, wmma::col_major> bf;
                wmma::load_matrix_sync(bf, &sB[(ng * 2 + t) * 16][kk], 40);
                wmma::mma_sync(cf[t], af, bf, cf[t]);
            }
        }
        __syncthreads();
    }

    #pragma unroll
    for (int t = 0; t < 2; t++)
        wmma::store_matrix_sync(&g_gates[(bm + mt * 16) * GATES + bn + (ng * 2 + t) * 16],
                                cf[t], GATES, wmma::mem_row_major);
}

// --------------------------- LSTM pointwise (adds bias) ----------------------
__global__ void lstm_pw_kernel() {
    int idx = blockIdx.x * blockDim.x + threadIdx.x;
    int b = idx >> 9;
    int d = idx & 511;
    const float* gr = g_gates + b * GATES + d;
    float i = sigm(gr[0]    + g_bias[d]);
    float f = sigm(gr[512]  + g_bias[512 + d]);
    float g = tanhf(gr[1024] + g_bias[1024 + d]);
    float o = sigm(gr[1536] + g_bias[1536 + d]);
    float c = f * g_c[idx] + i * g;
    g_c[idx] = c;
    float h = o * tanhf(c);
    g_hr[b * 1024 + d] = h;                       // q = h into hr[:, :512]
    g_hr16[b * 1024 + d] = __float2half_rn(h);
}

// ---------- attention step 0: fp32 sweep + write fp16 copy of x --------------
// Warp-per-node online softmax; col layout slot j*4+c <-> column 128*j+4*lane+c.
__global__ void __launch_bounds__(512, 2) attn0_kernel(const float* __restrict__ x) {
    const int chunk = blockIdx.x;
    const int i0 = chunk * CHUNK;
    const int i1 = min(i0 + CHUNK, N_NODES);
    const int tid  = threadIdx.x;
    const int wid  = tid >> 5;
    const int lane = tid & 31;

    __shared__ __align__(16) float sm_q[D_IN];
    __shared__ float  sm_m[16], sm_d[16], sm_scale[16];
    __shared__ __align__(16) float4 sm_r[16][128];

    int lo = 0, hi = B_GRAPHS;
    while (lo < hi) {
        int mid = (lo + hi) >> 1;
        if (g_off[mid + 1] <= i0) lo = mid + 1; else hi = mid;
    }
    int b = lo;

    while (b < B_GRAPHS && g_off[b] < i1) {
        const int s0 = max(g_off[b], i0);
        const int s1 = min(g_off[b + 1], i1);
        if (s1 > s0) {
            sm_q[tid] = g_hr[b * 1024 + tid];
            __syncthreads();
            const float4* q4 = (const float4*)sm_q;

            float m = -CUDART_INF_F, denom = 0.0f;
            float r[16];
            #pragma unroll
            for (int k = 0; k < 16; k++) r[k] = 0.0f;

            for (int n = s0 + wid; n < s1; n += 16) {
                const float4* xr = (const float4*)(x + (size_t)n * D_IN);
                float xv[16];
                #pragma unroll
                for (int j = 0; j < 4; j++) {
                    float4 v = __ldcs(xr + j * 32 + lane);
                    xv[j*4+0] = v.x; xv[j*4+1] = v.y;
                    xv[j*4+2] = v.z; xv[j*4+3] = v.w;
                }
                {
                    uint2* row16 = (uint2*)(g_x16 + (size_t)n * D_IN);
                    #pragma unroll
                    for (int j = 0; j < 4; j++) {
                        __half2 h0 = __floats2half2_rn(xv[j*4+0], xv[j*4+1]);
                        __half2 h1 = __floats2half2_rn(xv[j*4+2], xv[j*4+3]);
                        uint2 px;
                        px.x = *(unsigned*)&h0;
                        px.y = *(unsigned*)&h1;
                        row16[j * 32 + lane] = px;
                    }
                }

                float p = 0.0f;
                #pragma unroll
                for (int j = 0; j < 4; j++) {
                    float4 qv = q4[j * 32 + lane];
                    p = fmaf(xv[j*4+0], qv.x, p);
                    p = fmaf(xv[j*4+1], qv.y, p);
                    p = fmaf(xv[j*4+2], qv.z, p);
                    p = fmaf(xv[j*4+3], qv.w, p);
                }
                #pragma unroll
                for (int o = 16; o; o >>= 1) p += __shfl_xor_sync(0xffffffffu, p, o);

                const float mn = fmaxf(m, p);
                const float sc = __expf(m - mn);
                const float wg = __expf(p - mn);
                denom = fmaf(denom, sc, wg);
                #pragma unroll
                for (int k = 0; k < 16; k++) r[k] = fmaf(r[k], sc, wg * xv[k]);
                m = mn;
            }

            if (lane == 0) { sm_m[wid] = m; sm_d[wid] = denom; }
            #pragma unroll
            for (int j = 0; j < 4; j++)
                sm_r[wid][j * 32 + lane] =
                    make_float4(r[j*4+0], r[j*4+1], r[j*4+2], r[j*4+3]);
            __syncthreads();

            float M = -CUDART_INF_F;
            #pragma unroll
            for (int w = 0; w < 16; w++) M = fmaxf(M, sm_m[w]);
            if (tid < 16)
                sm_scale[tid] = (sm_m[tid] == -CUDART_INF_F) ? 0.0f : __expf(sm_m[tid] - M);
            __syncthreads();

            float Dn = 0.0f, num = 0.0f;
            #pragma unroll
            for (int w = 0; w < 16; w++) {
                Dn  += sm_d[w] * sm_scale[w];
                num  = fmaf(((const float*)sm_r[w])[tid], sm_scale[w], num);
            }

            const int slot = chunk - g_off[b] / CHUNK;
            g_part_r[(b * MAX_SLOTS + slot) * D_IN + tid] = num;
            if (tid == 0) {
                g_part_m[b * MAX_SLOTS + slot] = M;
                g_part_d[b * MAX_SLOTS + slot] = Dn;
            }
            __syncthreads();
        }
        b++;
    }
}

// ---------- attention steps 1..5: fp16 sweep, 2 nodes per warp-iter ----------
// Lane owns cols [8*lane, 8*lane+8) and [256+8*lane, 256+8*lane+8).
__global__ void __launch_bounds__(512, 2) attn16_kernel() {
    const int chunk = blockIdx.x;
    const int i0 = chunk * CHUNK;
    const int i1 = min(i0 + CHUNK, N_NODES);
    const int tid  = threadIdx.x;
    const int wid  = tid >> 5;
    const int lane = tid & 31;

    __shared__ __align__(16) float sm_q[D_IN];
    __shared__ float  sm_m[16], sm_d[16], sm_scale[16];
    __shared__ __align__(16) float4 sm_r[16][128];

    int lo = 0, hi = B_GRAPHS;
    while (lo < hi) {
        int mid = (lo + hi) >> 1;
        if (g_off[mid + 1] <= i0) lo = mid + 1; else hi = mid;
    }
    int b = lo;

    while (b < B_GRAPHS && g_off[b] < i1) {
        const int s0 = max(g_off[b], i0);
        const int s1 = min(g_off[b + 1], i1);
        if (s1 > s0) {
            sm_q[tid] = g_hr[b * 1024 + tid];
            __syncthreads();
            float qf[16];
            #pragma unroll
            for (int k = 0; k < 8; k++) qf[k]     = sm_q[8 * lane + k];
            #pragma unroll
            for (int k = 0; k < 8; k++) qf[8 + k] = sm_q[256 + 8 * lane + k];

            float m = -CUDART_INF_F, denom = 0.0f;
            float r[16];
            #pragma unroll
            for (int k = 0; k < 16; k++) r[k] = 0.0f;

            for (int n = s0 + wid * 2; n < s1; n += 32) {
                const uint4* rowa = (const uint4*)(g_x16 + (size_t)n * D_IN);
                uint4 a0 = __ldcs(rowa + lane);
                uint4 a1 = __ldcs(rowa + 32 + lane);
                const bool has_b = (n + 1) < s1;
                uint4 b0, b1;
                if (has_b) {
                    const uint4* rowb = (const uint4*)(g_x16 + (size_t)(n + 1) * D_IN);
                    b0 = __ldcs(rowb + lane);
                    b1 = __ldcs(rowb + 32 + lane);
                }

                float xf[16];
                {
                    const unsigned* u = (const unsigned*)&a0;
                    #pragma unroll
                    for (int t = 0; t < 4; t++) {
                        float2 f = __half22float2(*(const __half2*)&u[t]);
                        xf[t*2+0] = f.x; xf[t*2+1] = f.y;
                    }
                    const unsigned* v = (const unsigned*)&a1;
                    #pragma unroll
                    for (int t = 0; t < 4; t++) {
                        float2 f = __half22float2(*(const __half2*)&v[t]);
                        xf[8+t*2+0] = f.x; xf[8+t*2+1] = f.y;
                    }
                }
                float p = 0.0f;
                #pragma unroll
                for (int k = 0; k < 16; k++) p = fmaf(xf[k], qf[k], p);
                #pragma unroll
                for (int o = 16; o; o >>= 1) p += __shfl_xor_sync(0xffffffffu, p, o);
                float mn = fmaxf(m, p);
                float sc = __expf(m - mn);
                float wg = __expf(p - mn);
                denom = fmaf(denom, sc, wg);
                #pragma unroll
                for (int k = 0; k < 16; k++) r[k] = fmaf(r[k], sc, wg * xf[k]);
                m = mn;

                if (has_b) {
                    float yf[16];
                    {
                        const unsigned* u = (const unsigned*)&b0;
                        #pragma unroll
                        for (int t = 0; t < 4; t++) {
                            float2 f = __half22float2(*(const __half2*)&u[t]);
                            yf[t*2+0] = f.x; yf[t*2+1] = f.y;
                        }
                        const unsigned* v = (const unsigned*)&b1;
                        #pragma unroll
                        for (int t = 0; t < 4; t++) {
                            float2 f = __half22float2(*(const __half2*)&v[t]);
                            yf[8+t*2+0] = f.x; yf[8+t*2+1] = f.y;
                        }
                    }
                    float pb = 0.0f;
                    #pragma unroll
                    for (int k = 0; k < 16; k++) pb = fmaf(yf[k], qf[k], pb);
                    #pragma unroll
                    for (int o = 16; o; o >>= 1) pb += __shfl_xor_sync(0xffffffffu, pb, o);
                    mn = fmaxf(m, pb);
                    sc = __expf(m - mn);
                    wg = __expf(pb - mn);
                    denom = fmaf(denom, sc, wg);
                    #pragma unroll
                    for (int k = 0; k < 16; k++) r[k] = fmaf(r[k], sc, wg * yf[k]);
                    m = mn;
                }
            }

            if (lane == 0) { sm_m[wid] = m; sm_d[wid] = denom; }
            {
                float* dst = (float*)sm_r[wid];
                #pragma unroll
                for (int k = 0; k < 8; k++) dst[8 * lane + k]       = r[k];
                #pragma unroll
                for (int k = 0; k < 8; k++) dst[256 + 8 * lane + k] = r[8 + k];
            }
            __syncthreads();

            float M = -CUDART_INF_F;
            #pragma unroll
            for (int w = 0; w < 16; w++) M = fmaxf(M, sm_m[w]);
            if (tid < 16)
                sm_scale[tid] = (sm_m[tid] == -CUDART_INF_F) ? 0.0f : __expf(sm_m[tid] - M);
            __syncthreads();

            float Dn = 0.0f, num = 0.0f;
            #pragma unroll
            for (int w = 0; w < 16; w++) {
                Dn  += sm_d[w] * sm_scale[w];
                num  = fmaf(((const float*)sm_r[w])[tid], sm_scale[w], num);
            }

            const int slot = chunk - g_off[b] / CHUNK;
            g_part_r[(b * MAX_SLOTS + slot) * D_IN + tid] = num;
            if (tid == 0) {
                g_part_m[b * MAX_SLOTS + slot] = M;
                g_part_d[b * MAX_SLOTS + slot] = Dn;
            }
            __syncthreads();
        }
        b++;
    }
}

// ------------------ attention pass 2: per-graph merge ------------------------
// Writes r (fp32 + fp16); on the final step also writes q_star to out.
__global__ void attn_merge_kernel(float* __restrict__ out) {
    const int b   = blockIdx.x;
    const int tid = threadIdx.x;
    const int o0 = g_off[b], o1 = g_off[b + 1];
    float res = 0.0f;
    if (o1 > o0) {
        const int J = (o1 - 1) / CHUNK - o0 / CHUNK + 1;
        float M = -CUDART_INF_F;
        for (int j = 0; j < J; j++) M = fmaxf(M, g_part_m[b * MAX_SLOTS + j]);
        float D = 0.0f, acc = 0.0f;
        for (int j = 0; j < J; j++) {
            const float s = __expf(g_part_m[b * MAX_SLOTS + j] - M);
            D   = fmaf(g_part_d[b * MAX_SLOTS + j], s, D);
            acc = fmaf(g_part_r[(b * MAX_SLOTS + j) * D_IN + tid], s, acc);
        }
        res = acc / (D + 1e-16f);
    }
    g_hr[b * 1024 + 512 + tid] = res;
    g_hr16[b * 1024 + 512 + tid] = __float2half_rn(res);
    if (out) {
        out[b * 1024 + tid]       = g_hr[b * 1024 + tid];   // h half
        out[b * 1024 + 512 + tid] = res;                    // r half
    }
}

// ------------------------------- launch --------------------------------------
extern "C" void kernel_launch(void* const* d_in, const int* in_sizes, int n_in,
                              void* d_out, int out_size) {
    const float* x     = (const float*)d_in[0];
    const int*   batch = (const int*)d_in[1];
    const float* w_ih  = (const float*)d_in[2];
    const float* w_hh  = (const float*)d_in[3];
    const float* b_ih  = (const float*)d_in[4];
    const float* b_hh  = (const float*)d_in[5];
    float* out = (float*)d_out;

    prep_w_kernel<<<(GATES * K_COMB) / 256, 256>>>(w_ih, w_hh, b_ih, b_hh);
    offsets_kernel<<<2, 160>>>(batch);
    lstm_init_kernel<<<B_GRAPHS, 512>>>();

    for (int s = 0; s < STEPS; s++) {
        if (s > 0) {
            gemm_tc_kernel<<<dim3(32, 4), 256>>>();
            lstm_pw_kernel<<<(B_GRAPHS * D_IN) / 512, 512>>>();
        }
        if (s == 0)
            attn0_kernel<<<N_CHUNKS, 512>>>(x);
        else
            attn16_kernel<<<N_CHUNKS, 512>>>();
        attn_merge_kernel<<<B_GRAPHS, 512>>>(s == STEPS - 1 ? out : nullptr);
    }
}